// round 12
// baseline (speedup 1.0000x reference)
#include <cuda_runtime.h>
#include <cstdint>

#define BB 4
#define SS 2048
#define DD 1024
#define UU 1024

// Scratch (static device globals; no runtime allocation allowed)
__device__ float g_q  [BB * SS * UU];
__device__ float g_k  [BB * SS * UU];
__device__ float g_vt [BB * UU * SS];   // V transposed per batch: [U, S]
__device__ float g_ctx[BB * SS * UU];   // aliased as rounded-X before GEMM 7
__device__ float g_wr [BB * SS * SS];   // tf32-rounded softmax weights
__device__ float g_wqt[UU * DD];
__device__ float g_wkt[UU * DD];
__device__ float g_wvt[UU * DD];
__device__ float g_wot[DD * UU];

__device__ __forceinline__ uint32_t f32_to_tf32(float x) {
    uint32_t r;
    asm("cvt.rna.tf32.f32 %0, %1;" : "=r"(r) : "f"(x));
    return r;
}
__device__ __forceinline__ float round_tf32(float x) {
    return __uint_as_float(f32_to_tf32(x));
}

__device__ __forceinline__ uint32_t smem_u32(const void* p) {
    uint32_t a;
    asm("{ .reg .u64 t; cvta.to.shared.u64 t, %1; cvt.u32.u64 %0, t; }" : "=r"(a) : "l"(p));
    return a;
}

__device__ __forceinline__ void cp16(uint32_t dst, const float* src) {
    asm volatile("cp.async.cg.shared.global [%0], [%1], 16;" :: "r"(dst), "l"(src));
}
#define CP_COMMIT()  asm volatile("cp.async.commit_group;" ::: "memory")
#define CP_WAIT1()   asm volatile("cp.async.wait_group 1;" ::: "memory")

__device__ __forceinline__ void ldsm_x4(uint32_t& r0, uint32_t& r1, uint32_t& r2, uint32_t& r3,
                                        uint32_t addr) {
    asm volatile("ldmatrix.sync.aligned.m8n8.x4.shared.b16 {%0,%1,%2,%3}, [%4];"
                 : "=r"(r0), "=r"(r1), "=r"(r2), "=r"(r3) : "r"(addr));
}

__device__ __forceinline__ void mma_tf32_16x8x8(float* c, const uint32_t* a, const uint32_t* b) {
    asm volatile(
        "mma.sync.aligned.m16n8k8.row.col.f32.tf32.tf32.f32 "
        "{%0,%1,%2,%3}, {%4,%5,%6,%7}, {%8,%9}, {%0,%1,%2,%3};"
        : "+f"(c[0]), "+f"(c[1]), "+f"(c[2]), "+f"(c[3])
        : "r"(a[0]), "r"(a[1]), "r"(a[2]), "r"(a[3]), "r"(b[0]), "r"(b[1]));
}

// ---------------------------------------------------------------------------
// tf32 mma.sync GEMM:  C[M,N] = alpha * A[M,K] * B[N,K]^T (+ bias[n])
// Inputs must already be tf32-rounded fp32.
// CTA tile 256x128, BK=32, 256 threads, warps 4(M)x2(N), warp tile 64x64
// (4x8 m16n8k8). 3-stage cp.async pipeline, ldmatrix feed, pitch-36 rows.
// ---------------------------------------------------------------------------
#define PITCH 36
#define A_TILE_FLOATS (256 * PITCH)             // 9216
#define B_TILE_FLOATS (128 * PITCH)             // 4608
#define A_TILE_BYTES  (A_TILE_FLOATS * 4)       // 36864
#define B_TILE_BYTES  (B_TILE_FLOATS * 4)       // 18432
#define STAGE_BYTES   (A_TILE_BYTES + B_TILE_BYTES)   // 55296
#define STAGES 3
#define SMEM_TOTAL (STAGES * STAGE_BYTES)       // 165888

template <bool HASBIAS, bool HASALPHA, bool ROUNDOUT>
__global__ void __launch_bounds__(256, 1) tf32_gemm(
    const float* __restrict__ A, const float* __restrict__ B, float* __restrict__ C,
    int K, long lda, long ldb, long ldc,
    long sA, long sB, long sC,
    const float* __restrict__ bias, const float* __restrict__ alpha_ptr)
{
    extern __shared__ float smem[];
    const uint32_t smem32 = smem_u32(smem);

    const int tid  = threadIdx.x;
    const int wid  = tid >> 5;
    const int lane = tid & 31;
    const int wm   = wid >> 1;          // 0..3  (M warp)
    const int wn   = wid & 1;           // 0..1  (N warp)
    const int gr   = lane >> 2;         // 0..7
    const int gc   = lane & 3;          // 0..3

    A += (long)blockIdx.z * sA + (long)(blockIdx.y * 256) * lda;
    B += (long)blockIdx.z * sB + (long)(blockIdx.x * 128) * ldb;
    C += (long)blockIdx.z * sC;

    // ldmatrix per-lane source offsets (bytes within a tile)
    const int q  = lane >> 3;
    const int rr = lane & 7;
    uint32_t offA[4], offB[4];
#pragma unroll
    for (int mt = 0; mt < 4; ++mt)
        offA[mt] = (uint32_t)((wm * 64 + mt * 16 + (q & 1) * 8 + rr) * PITCH + (q >> 1) * 4) * 4u;
#pragma unroll
    for (int p = 0; p < 4; ++p)
        offB[p] = (uint32_t)((wn * 64 + p * 16 + (q >> 1) * 8 + rr) * PITCH + (q & 1) * 4) * 4u;

    // staging maps (per chunk, per thread): A: 8 x 16B, B: 4 x 16B
    int arow[8], aseg[8], brow[4], bseg[4];
#pragma unroll
    for (int i = 0; i < 8; ++i) {
        const int lin = tid + 256 * i;
        arow[i] = lin >> 3;
        aseg[i] = lin & 7;
    }
#pragma unroll
    for (int i = 0; i < 4; ++i) {
        const int lin = tid + 256 * i;
        brow[i] = lin >> 3;
        bseg[i] = lin & 7;
    }

    uint32_t aAddr[STAGES], bAddr[STAGES];
#pragma unroll
    for (int s = 0; s < STAGES; ++s) {
        aAddr[s] = smem32 + (uint32_t)s * STAGE_BYTES;
        bAddr[s] = aAddr[s] + A_TILE_BYTES;
    }

    float acc[4][8][4];
#pragma unroll
    for (int mt = 0; mt < 4; ++mt)
#pragma unroll
        for (int nt = 0; nt < 8; ++nt)
#pragma unroll
            for (int e = 0; e < 4; ++e) acc[mt][nt][e] = 0.0f;

    const int nch = K >> 5;

    auto issue = [&](int chunk, int stage) {
        const float* An = A + chunk * 32;
        const float* Bn = B + chunk * 32;
#pragma unroll
        for (int i = 0; i < 8; ++i)
            cp16(aAddr[stage] + (uint32_t)(arow[i] * PITCH + aseg[i] * 4) * 4u,
                 An + (long)arow[i] * lda + aseg[i] * 4);
#pragma unroll
        for (int i = 0; i < 4; ++i)
            cp16(bAddr[stage] + (uint32_t)(brow[i] * PITCH + bseg[i] * 4) * 4u,
                 Bn + (long)brow[i] * ldb + bseg[i] * 4);
    };

    issue(0, 0);
    CP_COMMIT();
    if (nch > 1) issue(1, 1);
    CP_COMMIT();

    for (int c = 0; c < nch; ++c) {
        CP_WAIT1();
        __syncthreads();

        if (c + 2 < nch) issue(c + 2, (c + 2) % STAGES);
        CP_COMMIT();

        const int st = c % STAGES;
        const uint32_t aB = aAddr[st];
        const uint32_t bB = bAddr[st];

#pragma unroll
        for (int ks = 0; ks < 4; ++ks) {
            uint32_t af[4][4], bf[8][2];
#pragma unroll
            for (int mt = 0; mt < 4; ++mt)
                ldsm_x4(af[mt][0], af[mt][1], af[mt][2], af[mt][3],
                        aB + offA[mt] + ks * 32u);
#pragma unroll
            for (int p = 0; p < 4; ++p)
                ldsm_x4(bf[2 * p][0], bf[2 * p][1], bf[2 * p + 1][0], bf[2 * p + 1][1],
                        bB + offB[p] + ks * 32u);
#pragma unroll
            for (int mt = 0; mt < 4; ++mt)
#pragma unroll
                for (int nt = 0; nt < 8; ++nt)
                    mma_tf32_16x8x8(acc[mt][nt], af[mt], bf[nt]);
        }
    }

    // Epilogue
    const float alpha = HASALPHA ? *alpha_ptr : 1.0f;
    const int row_base = blockIdx.y * 256 + wm * 64;
    const int col_base = blockIdx.x * 128 + wn * 64;

#pragma unroll
    for (int mt = 0; mt < 4; ++mt) {
#pragma unroll
        for (int nt = 0; nt < 8; ++nt) {
            const int r0 = row_base + mt * 16 + gr;
            const int cc = col_base + nt * 8 + 2 * gc;
            float2 v0, v1;
            v0.x = acc[mt][nt][0] * alpha;
            v0.y = acc[mt][nt][1] * alpha;
            v1.x = acc[mt][nt][2] * alpha;
            v1.y = acc[mt][nt][3] * alpha;
            if (HASBIAS) {
                const float2 bv = *(const float2*)(bias + cc);
                v0.x += bv.x; v0.y += bv.y;
                v1.x += bv.x; v1.y += bv.y;
            }
            if (ROUNDOUT) {
                v0.x = round_tf32(v0.x); v0.y = round_tf32(v0.y);
                v1.x = round_tf32(v1.x); v1.y = round_tf32(v1.y);
            }
            *(float2*)(C + (long)r0 * ldc + cc)       = v0;
            *(float2*)(C + (long)(r0 + 8) * ldc + cc) = v1;
        }
    }
}

// ---------------------------------------------------------------------------
// Fused 4-way 1024x1024 transpose with tf32 rounding (one launch, z selects)
// ---------------------------------------------------------------------------
__global__ void __launch_bounds__(256) transpose4(
    const float* __restrict__ s0, const float* __restrict__ s1,
    const float* __restrict__ s2, const float* __restrict__ s3,
    float* __restrict__ d0, float* __restrict__ d1,
    float* __restrict__ d2, float* __restrict__ d3)
{
    const float* in;
    float* out;
    switch (blockIdx.z) {
        case 0:  in = s0; out = d0; break;
        case 1:  in = s1; out = d1; break;
        case 2:  in = s2; out = d2; break;
        default: in = s3; out = d3; break;
    }
    __shared__ float t[32][33];
    const int bx = blockIdx.x * 32, by = blockIdx.y * 32;
    const int txx = threadIdx.x, tyy = threadIdx.y;
#pragma unroll
    for (int i = 0; i < 4; ++i)
        t[tyy + 8 * i][txx] = in[(long)(by + tyy + 8 * i) * 1024 + bx + txx];
    __syncthreads();
#pragma unroll
    for (int i = 0; i < 4; ++i)
        out[(long)(bx + tyy + 8 * i) * 1024 + by + txx] = round_tf32(t[txx][tyy + 8 * i]);
}

// ---------------------------------------------------------------------------
// Elementwise tf32-rounded copy (float4 granularity)
// ---------------------------------------------------------------------------
__global__ void __launch_bounds__(256) round_copy(
    const float* __restrict__ in, float* __restrict__ out)
{
    const long i = ((long)blockIdx.x * 256 + threadIdx.x) * 4;
    float4 v = *(const float4*)(in + i);
    v.x = round_tf32(v.x); v.y = round_tf32(v.y);
    v.z = round_tf32(v.z); v.w = round_tf32(v.w);
    *(float4*)(out + i) = v;
}

// ---------------------------------------------------------------------------
// Softmax over rows of 2048; writes exact weights AND tf32-rounded copy.
// ---------------------------------------------------------------------------
__global__ void __launch_bounds__(256) softmax2048(
    float* __restrict__ data, float* __restrict__ rounded)
{
    __shared__ float red[8];
    float* row  = data    + (long)blockIdx.x * 2048;
    float* rrow = rounded + (long)blockIdx.x * 2048;
    const int tid = threadIdx.x;

    float v[8];
    float m = -3.4e38f;
#pragma unroll
    for (int i = 0; i < 8; ++i) { v[i] = row[tid + 256 * i]; m = fmaxf(m, v[i]); }
#pragma unroll
    for (int s = 16; s > 0; s >>= 1) m = fmaxf(m, __shfl_xor_sync(0xFFFFFFFF, m, s));
    if ((tid & 31) == 0) red[tid >> 5] = m;
    __syncthreads();
    m = red[tid & 7];
#pragma unroll
    for (int s = 4; s > 0; s >>= 1) m = fmaxf(m, __shfl_xor_sync(0xFFFFFFFF, m, s));
    __syncthreads();

    float sum = 0.0f;
#pragma unroll
    for (int i = 0; i < 8; ++i) { v[i] = __expf(v[i] - m); sum += v[i]; }
#pragma unroll
    for (int s = 16; s > 0; s >>= 1) sum += __shfl_xor_sync(0xFFFFFFFF, sum, s);
    if ((tid & 31) == 0) red[tid >> 5] = sum;
    __syncthreads();
    sum = red[tid & 7];
#pragma unroll
    for (int s = 4; s > 0; s >>= 1) sum += __shfl_xor_sync(0xFFFFFFFF, sum, s);

    const float inv = 1.0f / sum;
#pragma unroll
    for (int i = 0; i < 8; ++i) {
        const float w = v[i] * inv;
        row[tid + 256 * i]  = w;
        rrow[tid + 256 * i] = round_tf32(w);
    }
}

// ---------------------------------------------------------------------------
// kernel_launch
// inputs: inputs[B,S,D], Wq[D,U], Wk[D,U], Wv[D,U], Wo[U,D], bo[D], scale
// output: [ output (B*S*D) | weights (B*S*S) ]
// ---------------------------------------------------------------------------
extern "C" void kernel_launch(void* const* d_in, const int* in_sizes, int n_in,
                              void* d_out, int out_size)
{
    const float* x     = (const float*)d_in[0];
    const float* Wq    = (const float*)d_in[1];
    const float* Wk    = (const float*)d_in[2];
    const float* Wv    = (const float*)d_in[3];
    const float* Wo    = (const float*)d_in[4];
    const float* bo    = (const float*)d_in[5];
    const float* scale = (const float*)d_in[6];

    float* out  = (float*)d_out;
    float* wout = (float*)d_out + (long)BB * SS * DD;

    float *qp, *kp, *vt, *ctx, *wr, *wqt, *wkt, *wvt, *wot;
    cudaGetSymbolAddress((void**)&qp,  g_q);
    cudaGetSymbolAddress((void**)&kp,  g_k);
    cudaGetSymbolAddress((void**)&vt,  g_vt);
    cudaGetSymbolAddress((void**)&ctx, g_ctx);
    cudaGetSymbolAddress((void**)&wr,  g_wr);
    cudaGetSymbolAddress((void**)&wqt, g_wqt);
    cudaGetSymbolAddress((void**)&wkt, g_wkt);
    cudaGetSymbolAddress((void**)&wvt, g_wvt);
    cudaGetSymbolAddress((void**)&wot, g_wot);

    float* xr = ctx;   // rounded X aliases g_ctx (dead until GEMM 7 writes it)

    cudaFuncSetAttribute(tf32_gemm<false, false, true>,
                         cudaFuncAttributeMaxDynamicSharedMemorySize, SMEM_TOTAL);
    cudaFuncSetAttribute(tf32_gemm<false, true, false>,
                         cudaFuncAttributeMaxDynamicSharedMemorySize, SMEM_TOTAL);
    cudaFuncSetAttribute(tf32_gemm<true, false, false>,
                         cudaFuncAttributeMaxDynamicSharedMemorySize, SMEM_TOTAL);

    // 0) Round X once (tf32-rounded fp32, raw-stageable)
    round_copy<<<(BB * SS * DD) / 1024, 256>>>(x, xr);

    // 1) Transpose all 4 weights with rounding (single launch, z=4)
    transpose4<<<dim3(32, 32, 4), dim3(32, 8)>>>(Wq, Wk, Wv, Wo, wqt, wkt, wvt, wot);

    const int M_all = BB * SS;  // 8192

    // 2) Q = Xr @ Wqt   (rounded output)
    tf32_gemm<false, false, true><<<dim3(UU / 128, M_all / 256, 1), 256, SMEM_TOTAL>>>(
        xr, wqt, qp, DD, DD, DD, UU, 0, 0, 0, nullptr, nullptr);
    // 3) K = Xr @ Wkt   (rounded output)
    tf32_gemm<false, false, true><<<dim3(UU / 128, M_all / 256, 1), 256, SMEM_TOTAL>>>(
        xr, wkt, kp, DD, DD, DD, UU, 0, 0, 0, nullptr, nullptr);
    // 4) Vt[b] = (X_b @ Wv)^T : A=Wvt [U,D], B=Xr_b [S,D]  (rounded output)
    tf32_gemm<false, false, true><<<dim3(SS / 128, UU / 256, BB), 256, SMEM_TOTAL>>>(
        wvt, xr, vt, DD, DD, DD, SS,
        0, (long)SS * DD, (long)UU * SS, nullptr, nullptr);
    // 5) scores[b] = scale * Q_b @ K_b^T  (exact output -> weights)
    tf32_gemm<false, true, false><<<dim3(SS / 128, SS / 256, BB), 256, SMEM_TOTAL>>>(
        qp, kp, wout, UU, UU, UU, SS,
        (long)SS * UU, (long)SS * UU, (long)SS * SS, nullptr, scale);
    // 6) softmax: exact -> wout, rounded -> wr
    softmax2048<<<BB * SS, 256>>>(wout, wr);
    // 7) ctx[b] = weights_b @ V_b : A=wr_b [S,S], B=Vt_b [U,S]  (rounded output)
    tf32_gemm<false, false, true><<<dim3(UU / 128, SS / 256, BB), 256, SMEM_TOTAL>>>(
        wr, vt, ctx, SS, SS, SS, UU,
        (long)SS * SS, (long)UU * SS, (long)SS * UU, nullptr, nullptr);
    // 8) out = ctx @ Wot + bo  (exact output)
    tf32_gemm<true, false, false><<<dim3(DD / 128, M_all / 256, 1), 256, SMEM_TOTAL>>>(
        ctx, wot, out, UU, UU, UU, DD, 0, 0, 0, bo, nullptr);

    (void)in_sizes; (void)n_in; (void)out_size;
}

// round 13
// speedup vs baseline: 1.2835x; 1.2835x over previous
#include <cuda_runtime.h>
#include <cstdint>

#define BB 4
#define SS 2048
#define DD 1024
#define UU 1024

// Scratch (static device globals; no runtime allocation allowed)
__device__ float g_q  [BB * SS * UU];
__device__ float g_k  [BB * SS * UU];
__device__ float g_vt [BB * UU * SS];   // V transposed per batch: [U, S]
__device__ float g_ctx[BB * SS * UU];   // aliased as rounded-X before GEMM 7
__device__ float g_wr [BB * SS * SS];   // tf32-rounded softmax weights
__device__ float g_wqt[UU * DD];
__device__ float g_wkt[UU * DD];
__device__ float g_wvt[UU * DD];
__device__ float g_wot[DD * UU];

__device__ __forceinline__ uint32_t f32_to_tf32(float x) {
    uint32_t r;
    asm("cvt.rna.tf32.f32 %0, %1;" : "=r"(r) : "f"(x));
    return r;
}
__device__ __forceinline__ float round_tf32(float x) {
    return __uint_as_float(f32_to_tf32(x));
}

__device__ __forceinline__ uint32_t smem_u32(const void* p) {
    uint32_t a;
    asm("{ .reg .u64 t; cvta.to.shared.u64 t, %1; cvt.u32.u64 %0, t; }" : "=r"(a) : "l"(p));
    return a;
}

__device__ __forceinline__ void cp16(uint32_t dst, const float* src) {
    asm volatile("cp.async.cg.shared.global [%0], [%1], 16;" :: "r"(dst), "l"(src));
}
#define CP_COMMIT()  asm volatile("cp.async.commit_group;" ::: "memory")
#define CP_WAIT1()   asm volatile("cp.async.wait_group 1;" ::: "memory")

__device__ __forceinline__ void ldsm_x4(uint32_t& r0, uint32_t& r1, uint32_t& r2, uint32_t& r3,
                                        uint32_t addr) {
    asm volatile("ldmatrix.sync.aligned.m8n8.x4.shared.b16 {%0,%1,%2,%3}, [%4];"
                 : "=r"(r0), "=r"(r1), "=r"(r2), "=r"(r3) : "r"(addr));
}

__device__ __forceinline__ void mma_tf32_16x8x8(float* c, const uint32_t* a, const uint32_t* b) {
    asm volatile(
        "mma.sync.aligned.m16n8k8.row.col.f32.tf32.tf32.f32 "
        "{%0,%1,%2,%3}, {%4,%5,%6,%7}, {%8,%9}, {%0,%1,%2,%3};"
        : "+f"(c[0]), "+f"(c[1]), "+f"(c[2]), "+f"(c[3])
        : "r"(a[0]), "r"(a[1]), "r"(a[2]), "r"(a[3]), "r"(b[0]), "r"(b[1]));
}

// ---------------------------------------------------------------------------
// tf32 mma.sync GEMM:  C[M,N] = alpha * A[M,K] * B[N,K]^T (+ bias[n])
// Inputs must already be tf32-rounded fp32.
// CTA tile 128x128, BK=32, 256 threads, warps 2(M)x4(N), warp tile 64x32.
// 3-stage cp.async pipeline, ldmatrix feed, pitch-36 rows.
// __launch_bounds__(256, 2): reg cap 128 -> 2 CTAs/SM (16 warps).
// ---------------------------------------------------------------------------
#define PITCH 36
#define TILE_FLOATS (128 * PITCH)           // 4608
#define TILE_BYTES  (TILE_FLOATS * 4)       // 18432
#define STAGE_BYTES (2 * TILE_BYTES)        // 36864
#define STAGES 3
#define SMEM_TOTAL  (STAGES * STAGE_BYTES)  // 110592

template <bool HASBIAS, bool HASALPHA, bool ROUNDOUT>
__global__ void __launch_bounds__(256, 2) tf32_gemm(
    const float* __restrict__ A, const float* __restrict__ B, float* __restrict__ C,
    int K, int lda, int ldb, int ldc,
    long sA, long sB, long sC,
    const float* __restrict__ bias, const float* __restrict__ alpha_ptr)
{
    extern __shared__ float smem[];
    const uint32_t smem32 = smem_u32(smem);

    const int tid  = threadIdx.x;
    const int wid  = tid >> 5;
    const int lane = tid & 31;
    const int wm   = wid >> 2;          // 0..1
    const int wn   = wid & 3;           // 0..3
    const int gr   = lane >> 2;         // 0..7
    const int gc   = lane & 3;          // 0..3

    A += (long)blockIdx.z * sA + (long)(blockIdx.y * 128) * lda;
    B += (long)blockIdx.z * sB + (long)(blockIdx.x * 128) * ldb;
    C += (long)blockIdx.z * sC;

    // ldmatrix per-lane smem offsets (bytes within a tile)
    const int q  = lane >> 3;
    const int rr = lane & 7;
    uint32_t offA[4], offB[2];
#pragma unroll
    for (int mt = 0; mt < 4; ++mt)
        offA[mt] = (uint32_t)((wm * 64 + mt * 16 + (q & 1) * 8 + rr) * PITCH + (q >> 1) * 4) * 4u;
#pragma unroll
    for (int p = 0; p < 2; ++p)
        offB[p] = (uint32_t)((wn * 32 + p * 16 + (q >> 1) * 8 + rr) * PITCH + (q & 1) * 4) * 4u;

    // staging maps: per chunk per thread, 4 x 16B per operand.
    // gmem offsets (int, within batch slice), smem offsets (bytes).
    int agoff[4], bgoff[4];
    uint32_t asoff[4];
#pragma unroll
    for (int i = 0; i < 4; ++i) {
        const int lin  = tid + 256 * i;
        const int row  = lin >> 3;
        const int seg  = lin & 7;
        agoff[i] = row * lda + seg * 4;
        bgoff[i] = row * ldb + seg * 4;
        asoff[i] = (uint32_t)(row * PITCH + seg * 4) * 4u;
    }

    float acc[4][4][4];
#pragma unroll
    for (int mt = 0; mt < 4; ++mt)
#pragma unroll
        for (int nt = 0; nt < 4; ++nt)
#pragma unroll
            for (int e = 0; e < 4; ++e) acc[mt][nt][e] = 0.0f;

    const int nch = K >> 5;

    // prologue: chunks 0,1 -> stages 0,1 (bulk issue)
    {
        const uint32_t a0 = smem32;
        const uint32_t b0 = smem32 + TILE_BYTES;
#pragma unroll
        for (int i = 0; i < 4; ++i) {
            cp16(a0 + asoff[i], A + agoff[i]);
            cp16(b0 + asoff[i], B + bgoff[i]);
        }
        CP_COMMIT();
        const uint32_t a1 = smem32 + STAGE_BYTES;
        const uint32_t b1 = a1 + TILE_BYTES;
#pragma unroll
        for (int i = 0; i < 4; ++i) {
            cp16(a1 + asoff[i], A + 32 + agoff[i]);
            cp16(b1 + asoff[i], B + 32 + bgoff[i]);
        }
        CP_COMMIT();
    }

    for (int c = 0; c < nch; ++c) {
        CP_WAIT1();
        __syncthreads();

        const int st = c % STAGES;
        const uint32_t aB = smem32 + (uint32_t)st * STAGE_BYTES;
        const uint32_t bB = aB + TILE_BYTES;

        const bool pf = (c + 2) < nch;
        const int pst = (c + 2) % STAGES;
        const uint32_t paB = smem32 + (uint32_t)pst * STAGE_BYTES;
        const uint32_t pbB = paB + TILE_BYTES;
        const float* An = A + (c + 2) * 32;
        const float* Bn = B + (c + 2) * 32;

#pragma unroll
        for (int ks = 0; ks < 4; ++ks) {
            // spread prefetch: 2 cps per ks (A[ks], B[ks])
            if (pf) {
                cp16(paB + asoff[ks], An + agoff[ks]);
                cp16(pbB + asoff[ks], Bn + bgoff[ks]);
            }
            uint32_t af[4][4], bf[4][2];
#pragma unroll
            for (int mt = 0; mt < 4; ++mt)
                ldsm_x4(af[mt][0], af[mt][1], af[mt][2], af[mt][3],
                        aB + offA[mt] + ks * 32u);
#pragma unroll
            for (int p = 0; p < 2; ++p)
                ldsm_x4(bf[2 * p][0], bf[2 * p][1], bf[2 * p + 1][0], bf[2 * p + 1][1],
                        bB + offB[p] + ks * 32u);
#pragma unroll
            for (int mt = 0; mt < 4; ++mt)
#pragma unroll
                for (int nt = 0; nt < 4; ++nt)
                    mma_tf32_16x8x8(acc[mt][nt], af[mt], bf[nt]);
        }
        CP_COMMIT();
    }

    // Epilogue
    const float alpha = HASALPHA ? *alpha_ptr : 1.0f;
    const int row_base = blockIdx.y * 128 + wm * 64;
    const int col_base = blockIdx.x * 128 + wn * 32;

#pragma unroll
    for (int mt = 0; mt < 4; ++mt) {
#pragma unroll
        for (int nt = 0; nt < 4; ++nt) {
            const int r0 = row_base + mt * 16 + gr;
            const int cc = col_base + nt * 8 + 2 * gc;
            float2 v0, v1;
            v0.x = acc[mt][nt][0] * alpha;
            v0.y = acc[mt][nt][1] * alpha;
            v1.x = acc[mt][nt][2] * alpha;
            v1.y = acc[mt][nt][3] * alpha;
            if (HASBIAS) {
                const float2 bv = *(const float2*)(bias + cc);
                v0.x += bv.x; v0.y += bv.y;
                v1.x += bv.x; v1.y += bv.y;
            }
            if (ROUNDOUT) {
                v0.x = round_tf32(v0.x); v0.y = round_tf32(v0.y);
                v1.x = round_tf32(v1.x); v1.y = round_tf32(v1.y);
            }
            *(float2*)(C + (long)r0 * ldc + cc)       = v0;
            *(float2*)(C + (long)(r0 + 8) * ldc + cc) = v1;
        }
    }
}

// ---------------------------------------------------------------------------
// Fused 4-way 1024x1024 transpose with tf32 rounding (one launch, z selects)
// ---------------------------------------------------------------------------
__global__ void __launch_bounds__(256) transpose4(
    const float* __restrict__ s0, const float* __restrict__ s1,
    const float* __restrict__ s2, const float* __restrict__ s3,
    float* __restrict__ d0, float* __restrict__ d1,
    float* __restrict__ d2, float* __restrict__ d3)
{
    const float* in;
    float* out;
    switch (blockIdx.z) {
        case 0:  in = s0; out = d0; break;
        case 1:  in = s1; out = d1; break;
        case 2:  in = s2; out = d2; break;
        default: in = s3; out = d3; break;
    }
    __shared__ float t[32][33];
    const int bx = blockIdx.x * 32, by = blockIdx.y * 32;
    const int txx = threadIdx.x, tyy = threadIdx.y;
#pragma unroll
    for (int i = 0; i < 4; ++i)
        t[tyy + 8 * i][txx] = in[(long)(by + tyy + 8 * i) * 1024 + bx + txx];
    __syncthreads();
#pragma unroll
    for (int i = 0; i < 4; ++i)
        out[(long)(bx + tyy + 8 * i) * 1024 + by + txx] = round_tf32(t[txx][tyy + 8 * i]);
}

// ---------------------------------------------------------------------------
// Elementwise tf32-rounded copy (float4 granularity)
// ---------------------------------------------------------------------------
__global__ void __launch_bounds__(256) round_copy(
    const float* __restrict__ in, float* __restrict__ out)
{
    const long i = ((long)blockIdx.x * 256 + threadIdx.x) * 4;
    float4 v = *(const float4*)(in + i);
    v.x = round_tf32(v.x); v.y = round_tf32(v.y);
    v.z = round_tf32(v.z); v.w = round_tf32(v.w);
    *(float4*)(out + i) = v;
}

// ---------------------------------------------------------------------------
// Softmax over rows of 2048; writes exact weights AND tf32-rounded copy.
// ---------------------------------------------------------------------------
__global__ void __launch_bounds__(256) softmax2048(
    float* __restrict__ data, float* __restrict__ rounded)
{
    __shared__ float red[8];
    float* row  = data    + (long)blockIdx.x * 2048;
    float* rrow = rounded + (long)blockIdx.x * 2048;
    const int tid = threadIdx.x;

    float v[8];
    float m = -3.4e38f;
#pragma unroll
    for (int i = 0; i < 8; ++i) { v[i] = row[tid + 256 * i]; m = fmaxf(m, v[i]); }
#pragma unroll
    for (int s = 16; s > 0; s >>= 1) m = fmaxf(m, __shfl_xor_sync(0xFFFFFFFF, m, s));
    if ((tid & 31) == 0) red[tid >> 5] = m;
    __syncthreads();
    m = red[tid & 7];
#pragma unroll
    for (int s = 4; s > 0; s >>= 1) m = fmaxf(m, __shfl_xor_sync(0xFFFFFFFF, m, s));
    __syncthreads();

    float sum = 0.0f;
#pragma unroll
    for (int i = 0; i < 8; ++i) { v[i] = __expf(v[i] - m); sum += v[i]; }
#pragma unroll
    for (int s = 16; s > 0; s >>= 1) sum += __shfl_xor_sync(0xFFFFFFFF, sum, s);
    if ((tid & 31) == 0) red[tid >> 5] = sum;
    __syncthreads();
    sum = red[tid & 7];
#pragma unroll
    for (int s = 4; s > 0; s >>= 1) sum += __shfl_xor_sync(0xFFFFFFFF, sum, s);

    const float inv = 1.0f / sum;
#pragma unroll
    for (int i = 0; i < 8; ++i) {
        const float w = v[i] * inv;
        row[tid + 256 * i]  = w;
        rrow[tid + 256 * i] = round_tf32(w);
    }
}

// ---------------------------------------------------------------------------
// kernel_launch
// inputs: inputs[B,S,D], Wq[D,U], Wk[D,U], Wv[D,U], Wo[U,D], bo[D], scale
// output: [ output (B*S*D) | weights (B*S*S) ]
// ---------------------------------------------------------------------------
extern "C" void kernel_launch(void* const* d_in, const int* in_sizes, int n_in,
                              void* d_out, int out_size)
{
    const float* x     = (const float*)d_in[0];
    const float* Wq    = (const float*)d_in[1];
    const float* Wk    = (const float*)d_in[2];
    const float* Wv    = (const float*)d_in[3];
    const float* Wo    = (const float*)d_in[4];
    const float* bo    = (const float*)d_in[5];
    const float* scale = (const float*)d_in[6];

    float* out  = (float*)d_out;
    float* wout = (float*)d_out + (long)BB * SS * DD;

    float *qp, *kp, *vt, *ctx, *wr, *wqt, *wkt, *wvt, *wot;
    cudaGetSymbolAddress((void**)&qp,  g_q);
    cudaGetSymbolAddress((void**)&kp,  g_k);
    cudaGetSymbolAddress((void**)&vt,  g_vt);
    cudaGetSymbolAddress((void**)&ctx, g_ctx);
    cudaGetSymbolAddress((void**)&wr,  g_wr);
    cudaGetSymbolAddress((void**)&wqt, g_wqt);
    cudaGetSymbolAddress((void**)&wkt, g_wkt);
    cudaGetSymbolAddress((void**)&wvt, g_wvt);
    cudaGetSymbolAddress((void**)&wot, g_wot);

    float* xr = ctx;   // rounded X aliases g_ctx (dead until GEMM 7 writes it)

    cudaFuncSetAttribute(tf32_gemm<false, false, true>,
                         cudaFuncAttributeMaxDynamicSharedMemorySize, SMEM_TOTAL);
    cudaFuncSetAttribute(tf32_gemm<false, true, false>,
                         cudaFuncAttributeMaxDynamicSharedMemorySize, SMEM_TOTAL);
    cudaFuncSetAttribute(tf32_gemm<true, false, false>,
                         cudaFuncAttributeMaxDynamicSharedMemorySize, SMEM_TOTAL);

    // 0) Round X once (tf32-rounded fp32, raw-stageable)
    round_copy<<<(BB * SS * DD) / 1024, 256>>>(x, xr);

    // 1) Transpose all 4 weights with rounding (single launch, z=4)
    transpose4<<<dim3(32, 32, 4), dim3(32, 8)>>>(Wq, Wk, Wv, Wo, wqt, wkt, wvt, wot);

    const int M_all = BB * SS;  // 8192

    // 2) Q = Xr @ Wqt   (rounded output)
    tf32_gemm<false, false, true><<<dim3(UU / 128, M_all / 128, 1), 256, SMEM_TOTAL>>>(
        xr, wqt, qp, DD, DD, DD, UU, 0, 0, 0, nullptr, nullptr);
    // 3) K = Xr @ Wkt   (rounded output)
    tf32_gemm<false, false, true><<<dim3(UU / 128, M_all / 128, 1), 256, SMEM_TOTAL>>>(
        xr, wkt, kp, DD, DD, DD, UU, 0, 0, 0, nullptr, nullptr);
    // 4) Vt[b] = (X_b @ Wv)^T : A=Wvt [U,D], B=Xr_b [S,D]  (rounded output)
    tf32_gemm<false, false, true><<<dim3(SS / 128, UU / 128, BB), 256, SMEM_TOTAL>>>(
        wvt, xr, vt, DD, DD, DD, SS,
        0, (long)SS * DD, (long)UU * SS, nullptr, nullptr);
    // 5) scores[b] = scale * Q_b @ K_b^T  (exact output -> weights)
    tf32_gemm<false, true, false><<<dim3(SS / 128, SS / 128, BB), 256, SMEM_TOTAL>>>(
        qp, kp, wout, UU, UU, UU, SS,
        (long)SS * UU, (long)SS * UU, (long)SS * SS, nullptr, scale);
    // 6) softmax: exact -> wout, rounded -> wr
    softmax2048<<<BB * SS, 256>>>(wout, wr);
    // 7) ctx[b] = weights_b @ V_b : A=wr_b [S,S], B=Vt_b [U,S]  (rounded output)
    tf32_gemm<false, false, true><<<dim3(UU / 128, SS / 128, BB), 256, SMEM_TOTAL>>>(
        wr, vt, ctx, SS, SS, SS, UU,
        (long)SS * SS, (long)UU * SS, (long)SS * UU, nullptr, nullptr);
    // 8) out = ctx @ Wot + bo  (exact output)
    tf32_gemm<true, false, false><<<dim3(DD / 128, M_all / 128, 1), 256, SMEM_TOTAL>>>(
        ctx, wot, out, UU, UU, UU, DD, 0, 0, 0, bo, nullptr);

    (void)in_sizes; (void)n_in; (void)out_size;
}

// round 14
// speedup vs baseline: 2.3213x; 1.8086x over previous
#include <cuda_runtime.h>
#include <cuda_fp16.h>
#include <cstdint>

#define BB 4
#define SS 2048
#define DD 1024
#define UU 1024

// Scratch (static device globals; no runtime allocation allowed). All half.
__device__ __half g_xh [BB * SS * DD];
__device__ __half g_q  [BB * SS * UU];
__device__ __half g_k  [BB * SS * UU];
__device__ __half g_vt [BB * UU * SS];   // V transposed per batch: [U, S]
__device__ __half g_ctx[BB * SS * UU];
__device__ __half g_wh [BB * SS * SS];   // fp16 softmax weights
__device__ __half g_wqt[UU * DD];
__device__ __half g_wkt[UU * DD];
__device__ __half g_wvt[UU * DD];
__device__ __half g_wot[DD * UU];

__device__ __forceinline__ uint32_t smem_u32(const void* p) {
    uint32_t a;
    asm("{ .reg .u64 t; cvta.to.shared.u64 t, %1; cvt.u32.u64 %0, t; }" : "=r"(a) : "l"(p));
    return a;
}

__device__ __forceinline__ void cp16(uint32_t dst, const void* src) {
    asm volatile("cp.async.cg.shared.global [%0], [%1], 16;" :: "r"(dst), "l"(src));
}
#define CP_COMMIT()  asm volatile("cp.async.commit_group;" ::: "memory")
#define CP_WAIT1()   asm volatile("cp.async.wait_group 1;" ::: "memory")

__device__ __forceinline__ void ldsm_x4(uint32_t& r0, uint32_t& r1, uint32_t& r2, uint32_t& r3,
                                        uint32_t addr) {
    asm volatile("ldmatrix.sync.aligned.m8n8.x4.shared.b16 {%0,%1,%2,%3}, [%4];"
                 : "=r"(r0), "=r"(r1), "=r"(r2), "=r"(r3) : "r"(addr));
}

__device__ __forceinline__ void mma_f16_16x8x16(float* c, const uint32_t* a, const uint32_t* b) {
    asm volatile(
        "mma.sync.aligned.m16n8k16.row.col.f32.f16.f16.f32 "
        "{%0,%1,%2,%3}, {%4,%5,%6,%7}, {%8,%9}, {%0,%1,%2,%3};"
        : "+f"(c[0]), "+f"(c[1]), "+f"(c[2]), "+f"(c[3])
        : "r"(a[0]), "r"(a[1]), "r"(a[2]), "r"(a[3]), "r"(b[0]), "r"(b[1]));
}

// ---------------------------------------------------------------------------
// fp16 mma.sync GEMM:  C[M,N] = alpha * A[M,K] * B[N,K]^T (+ bias[n])
// A, B half, row-major K-contiguous. CTA tile 128x128, BK=64 (halves),
// 256 threads, warps 2(M)x4(N), warp tile 64x32 (4x4 m16n8k16).
// 3-stage cp.async pipeline, ldmatrix feed, 144B SMEM rows.
// __launch_bounds__(256, 2): 2 CTAs/SM.
// OUTHALF: C is __half (rounded intermediates); else C is float.
// ---------------------------------------------------------------------------
#define ROWB   144u                         // bytes per SMEM row (64 halves + pad)
#define TILE_BYTES  (128u * ROWB)           // 18432
#define STAGE_BYTES (2u * TILE_BYTES)       // 36864
#define STAGES 3
#define SMEM_TOTAL  (STAGES * STAGE_BYTES)  // 110592

template <bool HASBIAS, bool HASALPHA, bool OUTHALF>
__global__ void __launch_bounds__(256, 2) h16_gemm(
    const __half* __restrict__ A, const __half* __restrict__ B, void* __restrict__ Cv,
    int K, int lda, int ldb, int ldc,
    long sA, long sB, long sC,
    const float* __restrict__ bias, const float* __restrict__ alpha_ptr)
{
    extern __shared__ char smem[];
    const uint32_t smem32 = smem_u32(smem);

    const int tid  = threadIdx.x;
    const int wid  = tid >> 5;
    const int lane = tid & 31;
    const int wm   = wid >> 2;          // 0..1
    const int wn   = wid & 3;           // 0..3
    const int gr   = lane >> 2;         // 0..7
    const int gc   = lane & 3;          // 0..3

    A += (long)blockIdx.z * sA + (long)(blockIdx.y * 128) * lda;
    B += (long)blockIdx.z * sB + (long)(blockIdx.x * 128) * ldb;

    // ldmatrix per-lane smem offsets (bytes within a tile)
    const int q  = lane >> 3;   // 0..3 selects 8x8 matrix
    const int rr = lane & 7;
    uint32_t offA[4], offB[2];
#pragma unroll
    for (int mt = 0; mt < 4; ++mt)   // A mt: rows {+0/+8} via q&1, k-half {0/8} via q>>1
        offA[mt] = (uint32_t)(wm * 64 + mt * 16 + (q & 1) * 8 + rr) * ROWB + (uint32_t)(q >> 1) * 16u;
#pragma unroll
    for (int p = 0; p < 2; ++p)      // B pair p: n-rows {+0/+8} via q>>1, k-half via q&1
        offB[p] = (uint32_t)(wn * 32 + p * 16 + (q >> 1) * 8 + rr) * ROWB + (uint32_t)(q & 1) * 16u;

    // staging: per chunk per thread, 4 x 16B per operand (tile = 128 rows x 128B)
    int agoff[4], bgoff[4];
    uint32_t asoff[4];
#pragma unroll
    for (int i = 0; i < 4; ++i) {
        const int lin = tid + 256 * i;
        const int row = lin >> 3;      // 0..127
        const int seg = lin & 7;       // 16B segment (8 halves)
        agoff[i] = row * lda + seg * 8;
        bgoff[i] = row * ldb + seg * 8;
        asoff[i] = (uint32_t)row * ROWB + (uint32_t)seg * 16u;
    }

    float acc[4][4][4];
#pragma unroll
    for (int mt = 0; mt < 4; ++mt)
#pragma unroll
        for (int nt = 0; nt < 4; ++nt)
#pragma unroll
            for (int e = 0; e < 4; ++e) acc[mt][nt][e] = 0.0f;

    const int nch = K >> 6;            // chunks of 64 halves

    // prologue: chunks 0,1 -> stages 0,1
    {
        const uint32_t a0 = smem32, b0 = smem32 + TILE_BYTES;
#pragma unroll
        for (int i = 0; i < 4; ++i) {
            cp16(a0 + asoff[i], A + agoff[i]);
            cp16(b0 + asoff[i], B + bgoff[i]);
        }
        CP_COMMIT();
        const uint32_t a1 = smem32 + STAGE_BYTES, b1 = a1 + TILE_BYTES;
#pragma unroll
        for (int i = 0; i < 4; ++i) {
            cp16(a1 + asoff[i], A + 64 + agoff[i]);
            cp16(b1 + asoff[i], B + 64 + bgoff[i]);
        }
        CP_COMMIT();
    }

    for (int c = 0; c < nch; ++c) {
        CP_WAIT1();
        __syncthreads();

        const int st = c % STAGES;
        const uint32_t aB = smem32 + (uint32_t)st * STAGE_BYTES;
        const uint32_t bB = aB + TILE_BYTES;

        const bool pf = (c + 2) < nch;
        const int pst = (c + 2) % STAGES;
        const uint32_t paB = smem32 + (uint32_t)pst * STAGE_BYTES;
        const uint32_t pbB = paB + TILE_BYTES;
        const __half* An = A + (c + 2) * 64;
        const __half* Bn = B + (c + 2) * 64;

#pragma unroll
        for (int ks = 0; ks < 4; ++ks) {     // each ks = k16
            if (pf) {
                cp16(paB + asoff[ks], An + agoff[ks]);
                cp16(pbB + asoff[ks], Bn + bgoff[ks]);
            }
            uint32_t af[4][4], bf[4][2];
#pragma unroll
            for (int mt = 0; mt < 4; ++mt)
                ldsm_x4(af[mt][0], af[mt][1], af[mt][2], af[mt][3],
                        aB + offA[mt] + ks * 32u);
#pragma unroll
            for (int p = 0; p < 2; ++p)
                ldsm_x4(bf[2 * p][0], bf[2 * p][1], bf[2 * p + 1][0], bf[2 * p + 1][1],
                        bB + offB[p] + ks * 32u);
#pragma unroll
            for (int mt = 0; mt < 4; ++mt)
#pragma unroll
                for (int nt = 0; nt < 4; ++nt)
                    mma_f16_16x8x16(acc[mt][nt], af[mt], bf[nt]);
        }
        CP_COMMIT();
    }

    // Epilogue
    const float alpha = HASALPHA ? *alpha_ptr : 1.0f;
    const int row_base = blockIdx.y * 128 + wm * 64;
    const int col_base = blockIdx.x * 128 + wn * 32;

#pragma unroll
    for (int mt = 0; mt < 4; ++mt) {
#pragma unroll
        for (int nt = 0; nt < 4; ++nt) {
            const int r0 = row_base + mt * 16 + gr;
            const int cc = col_base + nt * 8 + 2 * gc;
            float2 v0, v1;
            v0.x = acc[mt][nt][0] * alpha;
            v0.y = acc[mt][nt][1] * alpha;
            v1.x = acc[mt][nt][2] * alpha;
            v1.y = acc[mt][nt][3] * alpha;
            if (HASBIAS) {
                const float2 bv = *(const float2*)(bias + cc);
                v0.x += bv.x; v0.y += bv.y;
                v1.x += bv.x; v1.y += bv.y;
            }
            if (OUTHALF) {
                __half* C = (__half*)Cv + (long)blockIdx.z * sC;
                *(__half2*)(C + (long)r0 * ldc + cc)       = __floats2half2_rn(v0.x, v0.y);
                *(__half2*)(C + (long)(r0 + 8) * ldc + cc) = __floats2half2_rn(v1.x, v1.y);
            } else {
                float* C = (float*)Cv + (long)blockIdx.z * sC;
                *(float2*)(C + (long)r0 * ldc + cc)       = v0;
                *(float2*)(C + (long)(r0 + 8) * ldc + cc) = v1;
            }
        }
    }
}

// ---------------------------------------------------------------------------
// Fused 4-way 1024x1024 transpose fp32 -> fp16 (one launch, z selects)
// ---------------------------------------------------------------------------
__global__ void __launch_bounds__(256) transpose4(
    const float* __restrict__ s0, const float* __restrict__ s1,
    const float* __restrict__ s2, const float* __restrict__ s3,
    __half* __restrict__ d0, __half* __restrict__ d1,
    __half* __restrict__ d2, __half* __restrict__ d3)
{
    const float* in;
    __half* out;
    switch (blockIdx.z) {
        case 0:  in = s0; out = d0; break;
        case 1:  in = s1; out = d1; break;
        case 2:  in = s2; out = d2; break;
        default: in = s3; out = d3; break;
    }
    __shared__ float t[32][33];
    const int bx = blockIdx.x * 32, by = blockIdx.y * 32;
    const int txx = threadIdx.x, tyy = threadIdx.y;
#pragma unroll
    for (int i = 0; i < 4; ++i)
        t[tyy + 8 * i][txx] = in[(long)(by + tyy + 8 * i) * 1024 + bx + txx];
    __syncthreads();
#pragma unroll
    for (int i = 0; i < 4; ++i)
        out[(long)(bx + tyy + 8 * i) * 1024 + by + txx] = __float2half_rn(t[txx][tyy + 8 * i]);
}

// ---------------------------------------------------------------------------
// Elementwise fp32 -> fp16 convert (8 elems/thread)
// ---------------------------------------------------------------------------
__global__ void __launch_bounds__(256) convert_h(
    const float* __restrict__ in, __half* __restrict__ out)
{
    const long i = ((long)blockIdx.x * 256 + threadIdx.x) * 8;
    const float4 v0 = *(const float4*)(in + i);
    const float4 v1 = *(const float4*)(in + i + 4);
    __half2 h[4];
    h[0] = __floats2half2_rn(v0.x, v0.y);
    h[1] = __floats2half2_rn(v0.z, v0.w);
    h[2] = __floats2half2_rn(v1.x, v1.y);
    h[3] = __floats2half2_rn(v1.z, v1.w);
    *(uint4*)(out + i) = *(const uint4*)h;
}

// ---------------------------------------------------------------------------
// Softmax over rows of 2048; writes exact fp32 weights AND fp16 copy.
// ---------------------------------------------------------------------------
__global__ void __launch_bounds__(256) softmax2048(
    float* __restrict__ data, __half* __restrict__ halfcopy)
{
    __shared__ float red[8];
    float*  row  = data     + (long)blockIdx.x * 2048;
    __half* hrow = halfcopy + (long)blockIdx.x * 2048;
    const int tid = threadIdx.x;

    float v[8];
    float m = -3.4e38f;
#pragma unroll
    for (int i = 0; i < 8; ++i) { v[i] = row[tid + 256 * i]; m = fmaxf(m, v[i]); }
#pragma unroll
    for (int s = 16; s > 0; s >>= 1) m = fmaxf(m, __shfl_xor_sync(0xFFFFFFFF, m, s));
    if ((tid & 31) == 0) red[tid >> 5] = m;
    __syncthreads();
    m = red[tid & 7];
#pragma unroll
    for (int s = 4; s > 0; s >>= 1) m = fmaxf(m, __shfl_xor_sync(0xFFFFFFFF, m, s));
    __syncthreads();

    float sum = 0.0f;
#pragma unroll
    for (int i = 0; i < 8; ++i) { v[i] = __expf(v[i] - m); sum += v[i]; }
#pragma unroll
    for (int s = 16; s > 0; s >>= 1) sum += __shfl_xor_sync(0xFFFFFFFF, sum, s);
    if ((tid & 31) == 0) red[tid >> 5] = sum;
    __syncthreads();
    sum = red[tid & 7];
#pragma unroll
    for (int s = 4; s > 0; s >>= 1) sum += __shfl_xor_sync(0xFFFFFFFF, sum, s);

    const float inv = 1.0f / sum;
#pragma unroll
    for (int i = 0; i < 8; ++i) {
        const float w = v[i] * inv;
        row[tid + 256 * i]  = w;
        hrow[tid + 256 * i] = __float2half_rn(w);
    }
}

// ---------------------------------------------------------------------------
// kernel_launch
// inputs: inputs[B,S,D], Wq[D,U], Wk[D,U], Wv[D,U], Wo[U,D], bo[D], scale
// output: [ output (B*S*D) | weights (B*S*S) ]
// ---------------------------------------------------------------------------
extern "C" void kernel_launch(void* const* d_in, const int* in_sizes, int n_in,
                              void* d_out, int out_size)
{
    const float* x     = (const float*)d_in[0];
    const float* Wq    = (const float*)d_in[1];
    const float* Wk    = (const float*)d_in[2];
    const float* Wv    = (const float*)d_in[3];
    const float* Wo    = (const float*)d_in[4];
    const float* bo    = (const float*)d_in[5];
    const float* scale = (const float*)d_in[6];

    float* out  = (float*)d_out;
    float* wout = (float*)d_out + (long)BB * SS * DD;

    __half *xh, *qp, *kp, *vt, *ctx, *wh, *wqt, *wkt, *wvt, *wot;
    cudaGetSymbolAddress((void**)&xh,  g_xh);
    cudaGetSymbolAddress((void**)&qp,  g_q);
    cudaGetSymbolAddress((void**)&kp,  g_k);
    cudaGetSymbolAddress((void**)&vt,  g_vt);
    cudaGetSymbolAddress((void**)&ctx, g_ctx);
    cudaGetSymbolAddress((void**)&wh,  g_wh);
    cudaGetSymbolAddress((void**)&wqt, g_wqt);
    cudaGetSymbolAddress((void**)&wkt, g_wkt);
    cudaGetSymbolAddress((void**)&wvt, g_wvt);
    cudaGetSymbolAddress((void**)&wot, g_wot);

    cudaFuncSetAttribute(h16_gemm<false, false, true>,
                         cudaFuncAttributeMaxDynamicSharedMemorySize, SMEM_TOTAL);
    cudaFuncSetAttribute(h16_gemm<false, true, false>,
                         cudaFuncAttributeMaxDynamicSharedMemorySize, SMEM_TOTAL);
    cudaFuncSetAttribute(h16_gemm<true, false, false>,
                         cudaFuncAttributeMaxDynamicSharedMemorySize, SMEM_TOTAL);

    // 0) Convert X to fp16
    convert_h<<<(BB * SS * DD) / 2048, 256>>>(x, xh);

    // 1) Transpose + convert all 4 weights (single launch, z=4)
    transpose4<<<dim3(32, 32, 4), dim3(32, 8)>>>(Wq, Wk, Wv, Wo, wqt, wkt, wvt, wot);

    const int M_all = BB * SS;  // 8192

    // 2) Q = Xh @ Wqt   (half output)
    h16_gemm<false, false, true><<<dim3(UU / 128, M_all / 128, 1), 256, SMEM_TOTAL>>>(
        xh, wqt, qp, DD, DD, DD, UU, 0, 0, 0, nullptr, nullptr);
    // 3) K = Xh @ Wkt   (half output)
    h16_gemm<false, false, true><<<dim3(UU / 128, M_all / 128, 1), 256, SMEM_TOTAL>>>(
        xh, wkt, kp, DD, DD, DD, UU, 0, 0, 0, nullptr, nullptr);
    // 4) Vt[b] = (X_b @ Wv)^T : A=Wvt [U,D], B=Xh_b [S,D]  (half output)
    h16_gemm<false, false, true><<<dim3(SS / 128, UU / 128, BB), 256, SMEM_TOTAL>>>(
        wvt, xh, vt, DD, DD, DD, SS,
        0, (long)SS * DD, (long)UU * SS, nullptr, nullptr);
    // 5) scores[b] = scale * Q_b @ K_b^T  (exact fp32 -> weights)
    h16_gemm<false, true, false><<<dim3(SS / 128, SS / 128, BB), 256, SMEM_TOTAL>>>(
        qp, kp, wout, UU, UU, UU, SS,
        (long)SS * UU, (long)SS * UU, (long)SS * SS, nullptr, scale);
    // 6) softmax: exact -> wout, fp16 -> wh
    softmax2048<<<BB * SS, 256>>>(wout, wh);
    // 7) ctx[b] = weights_b @ V_b : A=wh_b [S,S], B=Vt_b [U,S]  (half output)
    h16_gemm<false, false, true><<<dim3(UU / 128, SS / 128, BB), 256, SMEM_TOTAL>>>(
        wh, vt, ctx, SS, SS, SS, UU,
        (long)SS * SS, (long)UU * SS, (long)SS * UU, nullptr, nullptr);
    // 8) out = ctx @ Wot + bo  (exact fp32)
    h16_gemm<true, false, false><<<dim3(DD / 128, M_all / 128, 1), 256, SMEM_TOTAL>>>(
        ctx, wot, out, UU, UU, UU, DD, 0, 0, 0, bo, nullptr);

    (void)in_sizes; (void)n_in; (void)out_size;
}